// round 1
// baseline (speedup 1.0000x reference)
#include <cuda_runtime.h>
#include <cstdint>

#define THREADS 256
#define KC      128
#define K_TOT   1024
#define DD      64
#define EPAD    68   // row stride (floats): 272B = 16B-aligned, 4-way store conflicts only

// Scratch (allocation-free): transposed codebook + half squared-norms
__device__ float g_emb_t[K_TOT * DD];
__device__ float g_esqh[K_TOT];

// Prep: transpose embeddings [D,K] -> [K,D] and compute 0.5*||e_k||^2
__global__ void vq_prep_kernel(const float* __restrict__ emb) {
    int k = blockIdx.x * blockDim.x + threadIdx.x;
    if (k >= K_TOT) return;
    float s = 0.f;
#pragma unroll
    for (int d = 0; d < DD; ++d) {
        float v = emb[d * K_TOT + k];      // coalesced across threads (consecutive k)
        g_emb_t[k * DD + d] = v;
        s += v * v;
    }
    g_esqh[k] = 0.5f * s;
}

__global__ __launch_bounds__(THREADS, 2)
void vq_main_kernel(const float* __restrict__ x,
                    const float* __restrict__ emb,
                    float* __restrict__ out) {
    __shared__ __align__(16) float s_e[KC * EPAD];
    __shared__ float s_esqh[K_TOT];
    __shared__ int   s_best[THREADS];

    const int row0 = blockIdx.x * THREADS;
    const int row  = row0 + threadIdx.x;

    // Load this thread's x row, packed into f32x2 register pairs (d-adjacent)
    unsigned long long x2[DD / 2];
    {
        const float4* xp = reinterpret_cast<const float4*>(x + (size_t)row * DD);
#pragma unroll
        for (int i = 0; i < DD / 4; ++i) {
            float4 v = xp[i];
            asm("mov.b64 %0, {%1, %2};" : "=l"(x2[2 * i])     : "f"(v.x), "f"(v.y));
            asm("mov.b64 %0, {%1, %2};" : "=l"(x2[2 * i + 1]) : "f"(v.z), "f"(v.w));
        }
    }
    for (int i = threadIdx.x; i < K_TOT; i += THREADS) s_esqh[i] = g_esqh[i];

    float best  = -1e30f;
    int   bestk = 0;

    for (int kc = 0; kc < K_TOT; kc += KC) {
        __syncthreads();
        // Cooperative transposed load of codebook chunk: global reads coalesced
        // (consecutive threads -> consecutive k within one d-row of emb)
#pragma unroll
        for (int t = 0; t < (KC * DD) / THREADS; ++t) {
            int idx = t * THREADS + threadIdx.x;
            int k   = idx & (KC - 1);
            int d   = idx >> 7;                 // idx / KC, KC == 128
            s_e[k * EPAD + d] = emb[d * K_TOT + kc + k];
        }
        __syncthreads();

#pragma unroll 4
        for (int k = 0; k < KC; ++k) {
            unsigned long long acc0 = 0ull, acc1 = 0ull;   // packed {0.f, 0.f}
            const ulonglong2* ep =
                reinterpret_cast<const ulonglong2*>(s_e + k * EPAD);
            // 16 LDS.128 broadcasts + 32 FFMA2 per k (packed along d)
#pragma unroll
            for (int j = 0; j < DD / 4; ++j) {
                ulonglong2 ev = ep[j];
                asm("fma.rn.f32x2 %0, %1, %2, %0;"
                    : "+l"(acc0) : "l"(x2[2 * j]),     "l"(ev.x));
                asm("fma.rn.f32x2 %0, %1, %2, %0;"
                    : "+l"(acc1) : "l"(x2[2 * j + 1]), "l"(ev.y));
            }
            float a0, a1, b0, b1;
            asm("mov.b64 {%0, %1}, %2;" : "=f"(a0), "=f"(a1) : "l"(acc0));
            asm("mov.b64 {%0, %1}, %2;" : "=f"(b0), "=f"(b1) : "l"(acc1));
            float sim   = (a0 + a1) + (b0 + b1);
            // distance = ||x||^2 + ||e||^2 - 2 sim  ->  argmax(sim - 0.5||e||^2)
            float score = sim - s_esqh[kc + k];
            if (score > best) { best = score; bestk = kc + k; }   // strict: first-index ties, matches argmin
        }
    }

    s_best[threadIdx.x] = bestk;
    __syncthreads();

    // Coalesced cooperative writeback: gather from transposed codebook (L2-resident)
#pragma unroll
    for (int t = 0; t < DD; ++t) {
        int idx = t * THREADS + threadIdx.x;
        int r   = idx >> 6;          // row within block
        int d   = idx & (DD - 1);
        out[(size_t)(row0 + r) * DD + d] = g_emb_t[s_best[r] * DD + d];
    }
}

extern "C" void kernel_launch(void* const* d_in, const int* in_sizes, int n_in,
                              void* d_out, int out_size) {
    const float* x   = (const float*)d_in[0];   // [B,H,W,D] = [N, 64]
    const float* emb = (const float*)d_in[1];   // [64, 1024]
    float*       out = (float*)d_out;

    const int N    = in_sizes[0] / DD;          // 131072
    const int grid = N / THREADS;               // 512

    vq_prep_kernel<<<(K_TOT + 255) / 256, 256>>>(emb);
    vq_main_kernel<<<grid, THREADS>>>(x, emb, out);
}

// round 5
// speedup vs baseline: 1.2066x; 1.2066x over previous
#include <cuda_runtime.h>
#include <cstdint>

#define THREADS 128
#define RPB     256          // rows per block (2 per thread)
#define KC      128
#define K_TOT   1024
#define DD      64
#define EPAD    68           // row stride in floats: 272B, 16B-aligned

// Scratch (allocation-free): transposed codebook + half squared-norms
__device__ float g_emb_t[K_TOT * DD];
__device__ float g_esqh[K_TOT];

__global__ void vq_prep_kernel(const float* __restrict__ emb) {
    int k = blockIdx.x * blockDim.x + threadIdx.x;
    if (k >= K_TOT) return;
    float s = 0.f;
#pragma unroll
    for (int d = 0; d < DD; ++d) {
        float v = emb[d * K_TOT + k];      // coalesced across threads
        g_emb_t[k * DD + d] = v;
        s += v * v;
    }
    g_esqh[k] = 0.5f * s;
}

__global__ __launch_bounds__(THREADS)
void vq_main_kernel(const float* __restrict__ x,
                    const float* __restrict__ emb,
                    float* __restrict__ out) {
    __shared__ __align__(16) float s_e[KC * EPAD];
    __shared__ float s_esqh[K_TOT];
    __shared__ int   s_best[RPB];

    const int tid  = threadIdx.x;
    const int row0 = blockIdx.x * RPB + tid;       // rows tid and tid+128
    const int row1 = row0 + THREADS;

    // Two x rows, packed into f32x2 register pairs (d-adjacent)
    unsigned long long xa[DD / 2], xb[DD / 2];
    {
        const float4* pa = reinterpret_cast<const float4*>(x + (size_t)row0 * DD);
        const float4* pb = reinterpret_cast<const float4*>(x + (size_t)row1 * DD);
#pragma unroll
        for (int i = 0; i < DD / 4; ++i) {
            float4 va = pa[i];
            float4 vb = pb[i];
            asm("mov.b64 %0, {%1, %2};" : "=l"(xa[2*i])   : "f"(va.x), "f"(va.y));
            asm("mov.b64 %0, {%1, %2};" : "=l"(xa[2*i+1]) : "f"(va.z), "f"(va.w));
            asm("mov.b64 %0, {%1, %2};" : "=l"(xb[2*i])   : "f"(vb.x), "f"(vb.y));
            asm("mov.b64 %0, {%1, %2};" : "=l"(xb[2*i+1]) : "f"(vb.z), "f"(vb.w));
        }
    }
    for (int i = tid; i < K_TOT; i += THREADS) s_esqh[i] = g_esqh[i];

    float bestA = -1e30f, bestB = -1e30f;
    int   bkA = 0, bkB = 0;

    for (int kc = 0; kc < K_TOT; kc += KC) {
        __syncthreads();
        // Cooperative transposed load: t-th iteration brings d=t row of the
        // codebook chunk; global reads fully coalesced (consecutive tid -> k).
#pragma unroll
        for (int t = 0; t < DD; ++t) {
            s_e[tid * EPAD + t] = emb[t * K_TOT + kc + tid];
        }
        __syncthreads();

#pragma unroll 2
        for (int k = 0; k < KC; ++k) {
            unsigned long long a0 = 0ull, a1 = 0ull;   // row0 acc (packed)
            unsigned long long b0 = 0ull, b1 = 0ull;   // row1 acc (packed)
            const ulonglong2* ep =
                reinterpret_cast<const ulonglong2*>(s_e + k * EPAD);
#pragma unroll
            for (int j = 0; j < DD / 4; ++j) {
                ulonglong2 ev = ep[j];                 // LDS.128 broadcast
                asm("fma.rn.f32x2 %0, %1, %2, %0;" : "+l"(a0) : "l"(xa[2*j]),   "l"(ev.x));
                asm("fma.rn.f32x2 %0, %1, %2, %0;" : "+l"(a1) : "l"(xa[2*j+1]), "l"(ev.y));
                asm("fma.rn.f32x2 %0, %1, %2, %0;" : "+l"(b0) : "l"(xb[2*j]),   "l"(ev.x));
                asm("fma.rn.f32x2 %0, %1, %2, %0;" : "+l"(b1) : "l"(xb[2*j+1]), "l"(ev.y));
            }
            float eq = s_esqh[kc + k];
            // packed pairwise combine, then final horizontal add
            asm("add.rn.f32x2 %0, %0, %1;" : "+l"(a0) : "l"(a1));
            asm("add.rn.f32x2 %0, %0, %1;" : "+l"(b0) : "l"(b1));
            float sA0, sA1, sB0, sB1;
            asm("mov.b64 {%0, %1}, %2;" : "=f"(sA0), "=f"(sA1) : "l"(a0));
            asm("mov.b64 {%0, %1}, %2;" : "=f"(sB0), "=f"(sB1) : "l"(b0));
            float scoreA = (sA0 + sA1) - eq;   // = sim - 0.5||e||^2 (argmax == argmin dist)
            float scoreB = (sB0 + sB1) - eq;
            if (scoreA > bestA) { bestA = scoreA; bkA = kc + k; }  // strict: first-index ties
            if (scoreB > bestB) { bestB = scoreB; bkB = kc + k; }
        }
    }

    s_best[tid]           = bkA;
    s_best[tid + THREADS] = bkB;
    __syncthreads();

    // Coalesced cooperative writeback from transposed codebook (L2-resident)
    const int rbase = blockIdx.x * RPB;
#pragma unroll
    for (int t = 0; t < (RPB * DD) / THREADS; ++t) {
        int idx = t * THREADS + tid;
        int r   = idx >> 6;              // row within block
        int d   = idx & (DD - 1);
        out[(size_t)(rbase + r) * DD + d] = g_emb_t[s_best[r] * DD + d];
    }
}

extern "C" void kernel_launch(void* const* d_in, const int* in_sizes, int n_in,
                              void* d_out, int out_size) {
    const float* x   = (const float*)d_in[0];   // [B,H,W,D] = [131072, 64]
    const float* emb = (const float*)d_in[1];   // [64, 1024]
    float*       out = (float*)d_out;

    const int N    = in_sizes[0] / DD;
    const int grid = N / RPB;                   // 512

    vq_prep_kernel<<<(K_TOT + 255) / 256, 256>>>(emb);
    vq_main_kernel<<<grid, THREADS>>>(x, emb, out);
}